// round 7
// baseline (speedup 1.0000x reference)
#include <cuda_runtime.h>
#include <cuda_bf16.h>
#include <cstdint>
#include <cstddef>

#define BATCH 4
#define C_IN  64
#define O_OUT 64
#define H_DIM 128
#define W_DIM 128

// ---------------- device scratch ----------------
__device__ __align__(1024) __nv_bfloat16 g_yhi[BATCH * H_DIM * W_DIM * C_IN];
__device__ __align__(1024) __nv_bfloat16 g_ylo[BATCH * H_DIM * W_DIM * C_IN];
// weights: [tap(9)][spl(2)][o(64)][c(64)] bf16
__device__ __align__(1024) __nv_bfloat16 g_w[18 * 64 * 64];

// ---------------- helpers ----------------
__device__ __forceinline__ uint32_t smem_u32(const void* p) {
    uint32_t a;
    asm("{ .reg .u64 t; cvta.to.shared.u64 t, %1; cvt.u32.u64 %0, t; }"
        : "=r"(a) : "l"(p));
    return a;
}
__device__ __forceinline__ void st128(uint32_t dst, uint4 v) {
    asm volatile("st.shared.v4.b32 [%0], {%1,%2,%3,%4};"
                 :: "r"(dst), "r"(v.x), "r"(v.y), "r"(v.z), "r"(v.w) : "memory");
}
__device__ __forceinline__ void cp16(uint32_t dst, const void* src) {
    asm volatile("cp.async.cg.shared.global [%0], [%1], 16;"
                 :: "r"(dst), "l"(__cvta_generic_to_global(src)) : "memory");
}
__device__ __forceinline__ void cp_commit_wait() {
    asm volatile("cp.async.commit_group;" ::: "memory");
    asm volatile("cp.async.wait_group 0;" ::: "memory");
}
__device__ __forceinline__ void ldsm_x4(uint32_t* r, uint32_t addr) {
    asm volatile("ldmatrix.sync.aligned.m8n8.x4.shared.b16 {%0,%1,%2,%3}, [%4];"
                 : "=r"(r[0]), "=r"(r[1]), "=r"(r[2]), "=r"(r[3]) : "r"(addr));
}
__device__ __forceinline__ void mma16816(float* c, const uint32_t* a, const uint32_t* b) {
    asm volatile(
        "mma.sync.aligned.m16n8k16.row.col.f32.bf16.bf16.f32 "
        "{%0,%1,%2,%3}, {%4,%5,%6,%7}, {%8,%9}, {%0,%1,%2,%3};"
        : "+f"(c[0]), "+f"(c[1]), "+f"(c[2]), "+f"(c[3])
        : "r"(a[0]), "r"(a[1]), "r"(a[2]), "r"(a[3]), "r"(b[0]), "r"(b[1]));
}

// ------- K1: weights repack (blocks 0..143) + y = x*f(alpha) transpose/split -------
__global__ __launch_bounds__(256)
void prep_kernel(const float* __restrict__ x, const float* __restrict__ alpha,
                 const float* __restrict__ wgt,
                 const float* __restrict__ pa, const float* __restrict__ pb,
                 const float* __restrict__ pc)
{
    __shared__ __align__(16) float fa[128];
    __shared__ __align__(16) float ysm[64][132];
    const int bid = blockIdx.x, b = bid >> 7, h = bid & 127;
    const int tid = threadIdx.x;
    const float ka = *pa, kb = *pb, kc = *pc;

    if (bid < 144) {   // folded wprep: 144*256 = 36864 = 64*64*9 elements
        const int e = bid * 256 + tid;
        const int o = e / 576, r = e % 576, c = r / 9, tap = r % 9;
        const float v = wgt[e];
        const __nv_bfloat16 hv = __float2bfloat16(v);
        const __nv_bfloat16 lv = __float2bfloat16(v - __bfloat162float(hv));
        g_w[((size_t)(tap * 2 + 0) * 64 + o) * 64 + c] = hv;
        g_w[((size_t)(tap * 2 + 1) * 64 + o) * 64 + c] = lv;
    }

    if (tid < 128) {
        const float av = alpha[(b * 128 + h) * 128 + tid];
        fa[tid] = (ka * av + kb) * av + kc;
    }
    __syncthreads();
    {
        const int c = tid >> 2, seg = (tid & 3) * 32;
        const float4* xr = (const float4*)(x + (((size_t)(b * 64 + c) * 128 + h) * 128 + seg));
        const float4* fr = (const float4*)(fa + seg);
        #pragma unroll
        for (int i = 0; i < 8; i++) {
            const float4 xv = xr[i], fv = fr[i];
            ysm[c][seg + 4 * i + 0] = xv.x * fv.x;
            ysm[c][seg + 4 * i + 1] = xv.y * fv.y;
            ysm[c][seg + 4 * i + 2] = xv.z * fv.z;
            ysm[c][seg + 4 * i + 3] = xv.w * fv.w;
        }
    }
    __syncthreads();
    if (tid < 128) {
        const int w = tid;
        uint32_t hibuf[32], lobuf[32];
        #pragma unroll
        for (int p = 0; p < 32; p++) {
            const float y0 = ysm[2 * p][w], y1 = ysm[2 * p + 1][w];
            const __nv_bfloat16 h0 = __float2bfloat16(y0);
            const __nv_bfloat16 h1 = __float2bfloat16(y1);
            const __nv_bfloat16 l0 = __float2bfloat16(y0 - __bfloat162float(h0));
            const __nv_bfloat16 l1 = __float2bfloat16(y1 - __bfloat162float(h1));
            hibuf[p] = (uint32_t)__bfloat16_as_ushort(h0) |
                       ((uint32_t)__bfloat16_as_ushort(h1) << 16);
            lobuf[p] = (uint32_t)__bfloat16_as_ushort(l0) |
                       ((uint32_t)__bfloat16_as_ushort(l1) << 16);
        }
        uint4* dhi = (uint4*)(g_yhi + ((size_t)((b * 128 + h) * 128 + w)) * 64);
        uint4* dlo = (uint4*)(g_ylo + ((size_t)((b * 128 + h) * 128 + w)) * 64);
        #pragma unroll
        for (int j = 0; j < 8; j++) {
            dhi[j] = make_uint4(hibuf[4*j], hibuf[4*j+1], hibuf[4*j+2], hibuf[4*j+3]);
            dlo[j] = make_uint4(lobuf[4*j], lobuf[4*j+1], lobuf[4*j+2], lobuf[4*j+3]);
        }
    }
}

// ---------------- K2: conv, di-outer staging + pipelined fragment loads ----------------
#define ASTR 144
#define AREG (130 * 144)            // 18720
#define B_OFF (2 * AREG)            // 37440
#define BTILE (64 * 144)            // 9216
#define SMEM_TOTAL (B_OFF + 6 * BTILE)   // 92736 -> 2 CTAs/SM

struct Frags { uint32_t ahi[2][4], alo[2][4], bhi[2][4], blo[2][4]; };

__global__ __launch_bounds__(256, 2)
void conv_kernel(const float* __restrict__ bias, float* __restrict__ out)
{
    extern __shared__ __align__(128) unsigned char smem[];
    const uint32_t sb = smem_u32(smem);
    const int tid = threadIdx.x, lane = tid & 31, wid = tid >> 5;
    const int bid = blockIdx.x, b = bid >> 7, h = bid & 127;
    const int m0 = (wid >> 1) * 32, n0 = (wid & 1) * 32;

    float acc[2][4][4] = {};

    // per-lane ldmatrix address components
    const int t8 = lane >> 3, r8 = lane & 7;
    const int a_row  = ((t8 & 1) << 3) + r8;
    const int a_koff = (t8 >> 1) << 3;
    const int b_orow = ((t8 >> 1) << 3) + r8;
    const int b_koff = (t8 & 1) << 3;

    // zero A halo rows 0 and 129 once (staging never touches them)
    if (tid < 32) {
        const int ch = tid & 7, rr = (tid >> 3) & 1, spl = tid >> 4;
        st128(sb + (uint32_t)spl * AREG + (uint32_t)(rr ? 129 : 0) * ASTR + ch * 16,
              make_uint4(0u, 0u, 0u, 0u));
    }

    // fragment loader for flattened step s: dj = s>>2, k0 = (s&3)*16
    auto load_step = [&](Frags& f, int s) {
        const int dj = s >> 2, k0 = (s & 3) << 4;
        #pragma unroll
        for (int mi = 0; mi < 2; mi++) {
            const uint32_t arow =
                (uint32_t)(m0 + mi * 16 + a_row + dj) * ASTR +
                (uint32_t)(k0 + a_koff) * 2;
            ldsm_x4(f.ahi[mi], sb + arow);
            ldsm_x4(f.alo[mi], sb + AREG + arow);
        }
        const uint32_t bb = sb + B_OFF + (uint32_t)(dj * 2) * BTILE;
        #pragma unroll
        for (int ni = 0; ni < 2; ni++) {
            const uint32_t brow =
                (uint32_t)(n0 + ni * 16 + b_orow) * ASTR +
                (uint32_t)(k0 + b_koff) * 2;
            ldsm_x4(f.bhi[ni], bb + brow);
            ldsm_x4(f.blo[ni], bb + BTILE + brow);
        }
    };
    auto mma_all = [&](Frags& f) {
        #pragma unroll
        for (int mi = 0; mi < 2; mi++)
            #pragma unroll
            for (int nj = 0; nj < 4; nj++) {
                mma16816(acc[mi][nj], f.ahi[mi], &f.bhi[nj >> 1][(nj & 1) * 2]);
                mma16816(acc[mi][nj], f.ahi[mi], &f.blo[nj >> 1][(nj & 1) * 2]);
                mma16816(acc[mi][nj], f.alo[mi], &f.bhi[nj >> 1][(nj & 1) * 2]);
            }
    };

    #pragma unroll 1
    for (int di = 0; di < 3; di++) {
        const int hs = h + di - 1;
        if ((unsigned)hs >= 128u) continue;
        __syncthreads();   // previous di's compute done before overwriting smem

        // ---- stage A via cp.async: 2 spl x 128 w x 8 chunks ----
        #pragma unroll
        for (int it = 0; it < 8; it++) {
            const int task = tid + it * 256;
            const int ch = task & 7, w = (task >> 3) & 127, spl = task >> 10;
            const __nv_bfloat16* pl = spl ? g_ylo : g_yhi;
            cp16(sb + (uint32_t)spl * AREG + (uint32_t)(w + 1) * ASTR + ch * 16,
                 (const uint4*)(pl + ((size_t)((b * 128 + hs) * 128 + w)) * 64) + ch);
        }
        // ---- stage B via cp.async: 6 tiles x 64 o x 8 chunks ----
        #pragma unroll
        for (int it = 0; it < 12; it++) {
            const int task = tid + it * 256;
            const int ch = task & 7, o = (task >> 3) & 63;
            const int spl = (task >> 9) & 1, dj = task >> 10;
            cp16(sb + B_OFF + (uint32_t)(dj * 2 + spl) * BTILE +
                     (uint32_t)o * ASTR + ch * 16,
                 (const uint4*)(g_w +
                     ((size_t)(((di * 3 + dj) * 2 + spl) * 64 + o)) * 64) + ch);
        }
        cp_commit_wait();
        __syncthreads();

        // ---- pipelined compute over 12 (dj,k0) steps ----
        Frags fA, fB;
        load_step(fA, 0);
        #pragma unroll 1
        for (int s = 0; s < 12; s += 2) {
            if (s + 1 < 12) load_step(fB, s + 1);
            mma_all(fA);
            if (s + 2 < 12) load_step(fA, s + 2);
            mma_all(fB);
        }
    }

    // ---- epilogue ----
    const int orow = lane >> 2, opair = (lane & 3) * 2;
    #pragma unroll
    for (int nj = 0; nj < 4; nj++) {
        const int o = n0 + nj * 8 + opair;
        const float bv0 = bias[o], bv1 = bias[o + 1];
        float* p0 = out + (((size_t)(b * 64 + o)) * 128 + h) * 128;
        float* p1 = p0 + 128 * 128;
        #pragma unroll
        for (int mi = 0; mi < 2; mi++) {
            const int w = m0 + mi * 16 + orow;
            p0[w]     = acc[mi][nj][0] + bv0;
            p1[w]     = acc[mi][nj][1] + bv1;
            p0[w + 8] = acc[mi][nj][2] + bv0;
            p1[w + 8] = acc[mi][nj][3] + bv1;
        }
    }
}

extern "C" void kernel_launch(void* const* d_in, const int* in_sizes, int n_in,
                              void* d_out, int out_size)
{
    const float* x     = (const float*)d_in[0];  // [4,64,128,128]
    const float* alpha = (const float*)d_in[1];  // [4,1,128,128]
    const float* wgt   = (const float*)d_in[2];  // [64,64,3,3]
    const float* bias  = (const float*)d_in[3];  // [64]
    const float* pa    = (const float*)d_in[4];
    const float* pb    = (const float*)d_in[5];
    const float* pc    = (const float*)d_in[6];
    float* out = (float*)d_out;                  // [4,64,128,128]

    cudaFuncSetAttribute(conv_kernel,
                         cudaFuncAttributeMaxDynamicSharedMemorySize, SMEM_TOTAL);

    prep_kernel<<<BATCH * H_DIM, 256>>>(x, alpha, wgt, pa, pb, pc);
    conv_kernel<<<BATCH * H_DIM, 256, SMEM_TOTAL>>>(bias, out);
}

// round 9
// speedup vs baseline: 1.1909x; 1.1909x over previous
#include <cuda_runtime.h>
#include <cuda_bf16.h>
#include <cstdint>
#include <cstddef>

#define BATCH 4
#define C_IN  64
#define O_OUT 64
#define H_DIM 128
#define W_DIM 128

// ---------------- device scratch ----------------
__device__ __align__(1024) __nv_bfloat16 g_yhi[BATCH * H_DIM * W_DIM * C_IN];
__device__ __align__(1024) __nv_bfloat16 g_ylo[BATCH * H_DIM * W_DIM * C_IN];
// weights: [tap(9)][spl(2)][o(64)][c(64)] bf16
__device__ __align__(1024) __nv_bfloat16 g_w[18 * 64 * 64];

// ---------------- helpers ----------------
__device__ __forceinline__ uint32_t smem_u32(const void* p) {
    uint32_t a;
    asm("{ .reg .u64 t; cvta.to.shared.u64 t, %1; cvt.u32.u64 %0, t; }"
        : "=r"(a) : "l"(p));
    return a;
}
__device__ __forceinline__ void st128(uint32_t dst, uint4 v) {
    asm volatile("st.shared.v4.b32 [%0], {%1,%2,%3,%4};"
                 :: "r"(dst), "r"(v.x), "r"(v.y), "r"(v.z), "r"(v.w) : "memory");
}
__device__ __forceinline__ void cp16(uint32_t dst, const void* src) {
    asm volatile("cp.async.cg.shared.global [%0], [%1], 16;"
                 :: "r"(dst), "l"(__cvta_generic_to_global(src)) : "memory");
}
__device__ __forceinline__ void cp_commit() {
    asm volatile("cp.async.commit_group;" ::: "memory");
}
__device__ __forceinline__ void cp_wait1() {
    asm volatile("cp.async.wait_group 1;" ::: "memory");
}
__device__ __forceinline__ void cp_wait0() {
    asm volatile("cp.async.wait_group 0;" ::: "memory");
}
__device__ __forceinline__ void ldsm_x4(uint32_t* r, uint32_t addr) {
    asm volatile("ldmatrix.sync.aligned.m8n8.x4.shared.b16 {%0,%1,%2,%3}, [%4];"
                 : "=r"(r[0]), "=r"(r[1]), "=r"(r[2]), "=r"(r[3]) : "r"(addr));
}
__device__ __forceinline__ void mma16816(float* c, const uint32_t* a, const uint32_t* b) {
    asm volatile(
        "mma.sync.aligned.m16n8k16.row.col.f32.bf16.bf16.f32 "
        "{%0,%1,%2,%3}, {%4,%5,%6,%7}, {%8,%9}, {%0,%1,%2,%3};"
        : "+f"(c[0]), "+f"(c[1]), "+f"(c[2]), "+f"(c[3])
        : "r"(a[0]), "r"(a[1]), "r"(a[2]), "r"(a[3]), "r"(b[0]), "r"(b[1]));
}

// ------- K1: weights repack (blocks 0..143) + y = x*f(alpha) transpose/split -------
__global__ __launch_bounds__(256)
void prep_kernel(const float* __restrict__ x, const float* __restrict__ alpha,
                 const float* __restrict__ wgt,
                 const float* __restrict__ pa, const float* __restrict__ pb,
                 const float* __restrict__ pc)
{
    __shared__ __align__(16) float fa[128];
    __shared__ __align__(16) float ysm[64][132];
    const int bid = blockIdx.x, b = bid >> 7, h = bid & 127;
    const int tid = threadIdx.x;
    const float ka = *pa, kb = *pb, kc = *pc;

    if (bid < 144) {   // folded wprep
        const int e = bid * 256 + tid;
        const int o = e / 576, r = e % 576, c = r / 9, tap = r % 9;
        const float v = wgt[e];
        const __nv_bfloat16 hv = __float2bfloat16(v);
        const __nv_bfloat16 lv = __float2bfloat16(v - __bfloat162float(hv));
        g_w[((size_t)(tap * 2 + 0) * 64 + o) * 64 + c] = hv;
        g_w[((size_t)(tap * 2 + 1) * 64 + o) * 64 + c] = lv;
    }

    if (tid < 128) {
        const float av = alpha[(b * 128 + h) * 128 + tid];
        fa[tid] = (ka * av + kb) * av + kc;
    }
    __syncthreads();
    {
        const int c = tid >> 2, seg = (tid & 3) * 32;
        const float4* xr = (const float4*)(x + (((size_t)(b * 64 + c) * 128 + h) * 128 + seg));
        const float4* fr = (const float4*)(fa + seg);
        #pragma unroll
        for (int i = 0; i < 8; i++) {
            const float4 xv = xr[i], fv = fr[i];
            ysm[c][seg + 4 * i + 0] = xv.x * fv.x;
            ysm[c][seg + 4 * i + 1] = xv.y * fv.y;
            ysm[c][seg + 4 * i + 2] = xv.z * fv.z;
            ysm[c][seg + 4 * i + 3] = xv.w * fv.w;
        }
    }
    __syncthreads();
    if (tid < 128) {
        const int w = tid;
        uint32_t hibuf[32], lobuf[32];
        #pragma unroll
        for (int p = 0; p < 32; p++) {
            const float y0 = ysm[2 * p][w], y1 = ysm[2 * p + 1][w];
            const __nv_bfloat16 h0 = __float2bfloat16(y0);
            const __nv_bfloat16 h1 = __float2bfloat16(y1);
            const __nv_bfloat16 l0 = __float2bfloat16(y0 - __bfloat162float(h0));
            const __nv_bfloat16 l1 = __float2bfloat16(y1 - __bfloat162float(h1));
            hibuf[p] = (uint32_t)__bfloat16_as_ushort(h0) |
                       ((uint32_t)__bfloat16_as_ushort(h1) << 16);
            lobuf[p] = (uint32_t)__bfloat16_as_ushort(l0) |
                       ((uint32_t)__bfloat16_as_ushort(l1) << 16);
        }
        uint4* dhi = (uint4*)(g_yhi + ((size_t)((b * 128 + h) * 128 + w)) * 64);
        uint4* dlo = (uint4*)(g_ylo + ((size_t)((b * 128 + h) * 128 + w)) * 64);
        #pragma unroll
        for (int j = 0; j < 8; j++) {
            dhi[j] = make_uint4(hibuf[4*j], hibuf[4*j+1], hibuf[4*j+2], hibuf[4*j+3]);
            dlo[j] = make_uint4(lobuf[4*j], lobuf[4*j+1], lobuf[4*j+2], lobuf[4*j+3]);
        }
    }
}

// ---------------- K2: conv, cp.async multistage over (di, K-half) units ----------------
// Unit buffer: A = 2 spl x 130 rows x 80B, B = 6 tiles x 64 rows x 80B.
#define ASTR 80
#define APL  (130 * 80)              // 10400 per spl plane
#define BOFF (2 * APL)               // 20800
#define BTL  (64 * 80)               // 5120 per tile
#define UNIT (BOFF + 6 * BTL)        // 51520
#define SMEM_TOTAL (2 * UNIT)        // 103040 -> 2 CTAs/SM

__global__ __launch_bounds__(256, 2)
void conv_kernel(const float* __restrict__ bias, float* __restrict__ out)
{
    extern __shared__ __align__(128) unsigned char smem[];
    const uint32_t sb = smem_u32(smem);
    const int tid = threadIdx.x, lane = tid & 31, wid = tid >> 5;
    const int bid = blockIdx.x, b = bid >> 7, h = bid & 127;
    const int m0 = (wid >> 1) * 32, n0 = (wid & 1) * 32;

    float acc[2][4][4] = {};

    const int t8 = lane >> 3, r8 = lane & 7;
    const int a_row  = ((t8 & 1) << 3) + r8;
    const int a_koff = (t8 >> 1) << 3;
    const int b_orow = ((t8 >> 1) << 3) + r8;
    const int b_koff = (t8 & 1) << 3;

    // zero A halo rows (0,129) of both spl planes in both buffers — never overwritten
    if (tid < 32) {
        const int ch = tid & 3, row = ((tid >> 2) & 1) ? 129 : 0;
        const int spl = (tid >> 3) & 1, bufi = tid >> 4;
        st128(sb + (uint32_t)bufi * UNIT + (uint32_t)spl * APL +
              (uint32_t)row * ASTR + ch * 16, make_uint4(0u, 0u, 0u, 0u));
    }
    __syncthreads();

    // valid units: (di, kh) pairs
    int ulist[6], nunits = 0;
    #pragma unroll
    for (int di = 0; di < 3; di++) {
        const int hs = h + di - 1;
        if ((unsigned)hs < 128u) { ulist[nunits++] = di * 2; ulist[nunits++] = di * 2 + 1; }
    }

    // stage one unit into a buffer (10 cp16 per thread)
    auto issue_unit = [&](int code, uint32_t bufbase) {
        const int di = code >> 1, kh = code & 1;
        const int hs = h + di - 1;
        // A: 1024 tasks: ch(4) x w(128) x spl(2)
        #pragma unroll
        for (int it = 0; it < 4; it++) {
            const int task = tid + it * 256;
            const int ch = task & 3, w = (task >> 2) & 127, spl = task >> 9;
            const __nv_bfloat16* pl = spl ? g_ylo : g_yhi;
            cp16(bufbase + (uint32_t)spl * APL + (uint32_t)(w + 1) * ASTR + ch * 16,
                 (const uint4*)(pl + ((size_t)((b * 128 + hs) * 128 + w)) * 64) +
                     (kh * 4 + ch));
        }
        // B: 1536 tasks: ch(4) x o(64) x spl(2) x dj(3)
        #pragma unroll
        for (int it = 0; it < 6; it++) {
            const int task = tid + it * 256;
            const int ch = task & 3, o = (task >> 2) & 63;
            const int spl = (task >> 8) & 1, dj = task >> 9;
            cp16(bufbase + BOFF + (uint32_t)(dj * 2 + spl) * BTL +
                     (uint32_t)o * ASTR + ch * 16,
                 (const uint4*)(g_w +
                     ((size_t)(((di * 3 + dj) * 2 + spl) * 64 + o)) * 64) +
                     (kh * 4 + ch));
        }
        cp_commit();
    };

    // prologue: fill stages 0 and 1
    issue_unit(ulist[0], sb);
    if (nunits > 1) issue_unit(ulist[1], sb + UNIT);

    #pragma unroll 1
    for (int u = 0; u < nunits; u++) {
        if (u + 1 < nunits) cp_wait1(); else cp_wait0();
        __syncthreads();

        const uint32_t bufbase = sb + (uint32_t)(u & 1) * UNIT;
        #pragma unroll 1
        for (int dj = 0; dj < 3; dj++) {
            const uint32_t bbh = bufbase + BOFF + (uint32_t)(dj * 2) * BTL;
            #pragma unroll
            for (int k0 = 0; k0 < 32; k0 += 16) {
                uint32_t ahi[2][4], alo[2][4], bhi[2][4], blo[2][4];
                #pragma unroll
                for (int mi = 0; mi < 2; mi++) {
                    const uint32_t arow =
                        (uint32_t)(m0 + mi * 16 + a_row + dj) * ASTR +
                        (uint32_t)(k0 + a_koff) * 2;
                    ldsm_x4(ahi[mi], bufbase + arow);
                    ldsm_x4(alo[mi], bufbase + APL + arow);
                }
                #pragma unroll
                for (int ni = 0; ni < 2; ni++) {
                    const uint32_t brow =
                        (uint32_t)(n0 + ni * 16 + b_orow) * ASTR +
                        (uint32_t)(k0 + b_koff) * 2;
                    ldsm_x4(bhi[ni], bbh + brow);
                    ldsm_x4(blo[ni], bbh + BTL + brow);
                }
                #pragma unroll
                for (int mi = 0; mi < 2; mi++)
                    #pragma unroll
                    for (int nj = 0; nj < 4; nj++) {
                        mma16816(acc[mi][nj], ahi[mi], &bhi[nj >> 1][(nj & 1) * 2]);
                        mma16816(acc[mi][nj], ahi[mi], &blo[nj >> 1][(nj & 1) * 2]);
                        mma16816(acc[mi][nj], alo[mi], &bhi[nj >> 1][(nj & 1) * 2]);
                    }
            }
        }
        __syncthreads();
        if (u + 2 < nunits) issue_unit(ulist[u + 2], bufbase);
    }

    // ---- epilogue ----
    const int orow = lane >> 2, opair = (lane & 3) * 2;
    #pragma unroll
    for (int nj = 0; nj < 4; nj++) {
        const int o = n0 + nj * 8 + opair;
        const float bv0 = bias[o], bv1 = bias[o + 1];
        float* p0 = out + (((size_t)(b * 64 + o)) * 128 + h) * 128;
        float* p1 = p0 + 128 * 128;
        #pragma unroll
        for (int mi = 0; mi < 2; mi++) {
            const int w = m0 + mi * 16 + orow;
            p0[w]     = acc[mi][nj][0] + bv0;
            p1[w]     = acc[mi][nj][1] + bv1;
            p0[w + 8] = acc[mi][nj][2] + bv0;
            p1[w + 8] = acc[mi][nj][3] + bv1;
        }
    }
}

extern "C" void kernel_launch(void* const* d_in, const int* in_sizes, int n_in,
                              void* d_out, int out_size)
{
    const float* x     = (const float*)d_in[0];  // [4,64,128,128]
    const float* alpha = (const float*)d_in[1];  // [4,1,128,128]
    const float* wgt   = (const float*)d_in[2];  // [64,64,3,3]
    const float* bias  = (const float*)d_in[3];  // [64]
    const float* pa    = (const float*)d_in[4];
    const float* pb    = (const float*)d_in[5];
    const float* pc    = (const float*)d_in[6];
    float* out = (float*)d_out;                  // [4,64,128,128]

    cudaFuncSetAttribute(conv_kernel,
                         cudaFuncAttributeMaxDynamicSharedMemorySize, SMEM_TOTAL);

    prep_kernel<<<BATCH * H_DIM, 256>>>(x, alpha, wgt, pa, pb, pc);
    conv_kernel<<<BATCH * H_DIM, 256, SMEM_TOTAL>>>(bias, out);
}

// round 10
// speedup vs baseline: 1.6763x; 1.4076x over previous
#include <cuda_runtime.h>
#include <cuda_fp16.h>
#include <cstdint>
#include <cstddef>

#define BATCH 4
#define C_IN  64
#define O_OUT 64
#define H_DIM 128
#define W_DIM 128

// ---------------- device scratch ----------------
// y = x*f(alpha), pixel-major [b][h][w][c], fp16 hi/lo split planes
__device__ __align__(1024) __half g_yhi[BATCH * H_DIM * W_DIM * C_IN];
__device__ __align__(1024) __half g_ylo[BATCH * H_DIM * W_DIM * C_IN];
// weights fp16 single-rounded: [tap(9)][o(64)][c(64)]
__device__ __align__(1024) __half g_w[9 * 64 * 64];

// ---------------- helpers ----------------
__device__ __forceinline__ uint32_t smem_u32(const void* p) {
    uint32_t a;
    asm("{ .reg .u64 t; cvta.to.shared.u64 t, %1; cvt.u32.u64 %0, t; }"
        : "=r"(a) : "l"(p));
    return a;
}
__device__ __forceinline__ void st128(uint32_t dst, uint4 v) {
    asm volatile("st.shared.v4.b32 [%0], {%1,%2,%3,%4};"
                 :: "r"(dst), "r"(v.x), "r"(v.y), "r"(v.z), "r"(v.w) : "memory");
}
__device__ __forceinline__ void cp16(uint32_t dst, const void* src) {
    asm volatile("cp.async.cg.shared.global [%0], [%1], 16;"
                 :: "r"(dst), "l"(__cvta_generic_to_global(src)) : "memory");
}
__device__ __forceinline__ void cp_commit() {
    asm volatile("cp.async.commit_group;" ::: "memory");
}
__device__ __forceinline__ void cp_wait1() {
    asm volatile("cp.async.wait_group 1;" ::: "memory");
}
__device__ __forceinline__ void cp_wait0() {
    asm volatile("cp.async.wait_group 0;" ::: "memory");
}
__device__ __forceinline__ void ldsm_x4(uint32_t* r, uint32_t addr) {
    asm volatile("ldmatrix.sync.aligned.m8n8.x4.shared.b16 {%0,%1,%2,%3}, [%4];"
                 : "=r"(r[0]), "=r"(r[1]), "=r"(r[2]), "=r"(r[3]) : "r"(addr));
}
__device__ __forceinline__ void mma16816(float* c, const uint32_t* a, const uint32_t* b) {
    asm volatile(
        "mma.sync.aligned.m16n8k16.row.col.f32.f16.f16.f32 "
        "{%0,%1,%2,%3}, {%4,%5,%6,%7}, {%8,%9}, {%0,%1,%2,%3};"
        : "+f"(c[0]), "+f"(c[1]), "+f"(c[2]), "+f"(c[3])
        : "r"(a[0]), "r"(a[1]), "r"(a[2]), "r"(a[3]), "r"(b[0]), "r"(b[1]));
}

// ------- K1: weights fp16 (blocks 0..143) + y = x*f(alpha) transpose/fp16-split -------
__global__ __launch_bounds__(256)
void prep_kernel(const float* __restrict__ x, const float* __restrict__ alpha,
                 const float* __restrict__ wgt,
                 const float* __restrict__ pa, const float* __restrict__ pb,
                 const float* __restrict__ pc)
{
    __shared__ __align__(16) float fa[128];
    __shared__ __align__(16) float ysm[64][132];
    const int bid = blockIdx.x, b = bid >> 7, h = bid & 127;
    const int tid = threadIdx.x;
    const float ka = *pa, kb = *pb, kc = *pc;

    if (bid < 144) {   // folded wprep: 36864 weight elements
        const int e = bid * 256 + tid;
        const int o = e / 576, r = e % 576, c = r / 9, tap = r % 9;
        g_w[((size_t)tap * 64 + o) * 64 + c] = __float2half(wgt[e]);
    }

    if (tid < 128) {
        const float av = alpha[(b * 128 + h) * 128 + tid];
        fa[tid] = (ka * av + kb) * av + kc;
    }
    __syncthreads();
    {
        const int c = tid >> 2, seg = (tid & 3) * 32;
        const float4* xr = (const float4*)(x + (((size_t)(b * 64 + c) * 128 + h) * 128 + seg));
        const float4* fr = (const float4*)(fa + seg);
        #pragma unroll
        for (int i = 0; i < 8; i++) {
            const float4 xv = xr[i], fv = fr[i];
            ysm[c][seg + 4 * i + 0] = xv.x * fv.x;
            ysm[c][seg + 4 * i + 1] = xv.y * fv.y;
            ysm[c][seg + 4 * i + 2] = xv.z * fv.z;
            ysm[c][seg + 4 * i + 3] = xv.w * fv.w;
        }
    }
    __syncthreads();
    if (tid < 128) {
        const int w = tid;
        uint32_t hibuf[32], lobuf[32];
        #pragma unroll
        for (int p = 0; p < 32; p++) {
            const float y0 = ysm[2 * p][w], y1 = ysm[2 * p + 1][w];
            const __half h0 = __float2half(y0);
            const __half h1 = __float2half(y1);
            const __half l0 = __float2half(y0 - __half2float(h0));
            const __half l1 = __float2half(y1 - __half2float(h1));
            hibuf[p] = (uint32_t)__half_as_ushort(h0) |
                       ((uint32_t)__half_as_ushort(h1) << 16);
            lobuf[p] = (uint32_t)__half_as_ushort(l0) |
                       ((uint32_t)__half_as_ushort(l1) << 16);
        }
        uint4* dhi = (uint4*)(g_yhi + ((size_t)((b * 128 + h) * 128 + w)) * 64);
        uint4* dlo = (uint4*)(g_ylo + ((size_t)((b * 128 + h) * 128 + w)) * 64);
        #pragma unroll
        for (int j = 0; j < 8; j++) {
            dhi[j] = make_uint4(hibuf[4*j], hibuf[4*j+1], hibuf[4*j+2], hibuf[4*j+3]);
            dlo[j] = make_uint4(lobuf[4*j], lobuf[4*j+1], lobuf[4*j+2], lobuf[4*j+3]);
        }
    }
}

// ---------------- K2: conv, cp.async multistage, 2-term fp16 ----------------
// Unit: A = 2 spl x 130 rows x 80B (K-half), B = 3 dj tiles x 64 rows x 80B.
#define ASTR 80
#define APL  (130 * 80)              // 10400 per spl plane
#define BOFF (2 * APL)               // 20800
#define BTL  (64 * 80)               // 5120 per tile
#define UNIT (BOFF + 3 * BTL)        // 36160
#define SMEM_TOTAL (2 * UNIT)        // 72320 -> 3 CTAs/SM

__global__ __launch_bounds__(256, 3)
void conv_kernel(const float* __restrict__ bias, float* __restrict__ out)
{
    extern __shared__ __align__(128) unsigned char smem[];
    const uint32_t sb = smem_u32(smem);
    const int tid = threadIdx.x, lane = tid & 31, wid = tid >> 5;
    const int bid = blockIdx.x, b = bid >> 7, h = bid & 127;
    const int m0 = (wid >> 1) * 32, n0 = (wid & 1) * 32;

    float acc[2][4][4] = {};

    const int t8 = lane >> 3, r8 = lane & 7;
    const int a_row  = ((t8 & 1) << 3) + r8;
    const int a_koff = (t8 >> 1) << 3;
    const int b_orow = ((t8 >> 1) << 3) + r8;
    const int b_koff = (t8 & 1) << 3;

    // zero A halo rows (0,129) of both spl planes in both buffers
    if (tid < 32) {
        const int ch = tid & 3, row = ((tid >> 2) & 1) ? 129 : 0;
        const int spl = (tid >> 3) & 1, bufi = tid >> 4;
        st128(sb + (uint32_t)bufi * UNIT + (uint32_t)spl * APL +
              (uint32_t)row * ASTR + ch * 16, make_uint4(0u, 0u, 0u, 0u));
    }
    __syncthreads();

    // valid units: (di, kh)
    int ulist[6], nunits = 0;
    #pragma unroll
    for (int di = 0; di < 3; di++) {
        const int hs = h + di - 1;
        if ((unsigned)hs < 128u) { ulist[nunits++] = di * 2; ulist[nunits++] = di * 2 + 1; }
    }

    auto issue_unit = [&](int code, uint32_t bufbase) {
        const int di = code >> 1, kh = code & 1;
        const int hs = h + di - 1;
        // A: 1024 tasks: ch(4) x w(128) x spl(2)
        #pragma unroll
        for (int it = 0; it < 4; it++) {
            const int task = tid + it * 256;
            const int ch = task & 3, w = (task >> 2) & 127, spl = task >> 9;
            const __half* pl = spl ? g_ylo : g_yhi;
            cp16(bufbase + (uint32_t)spl * APL + (uint32_t)(w + 1) * ASTR + ch * 16,
                 (const uint4*)(pl + ((size_t)((b * 128 + hs) * 128 + w)) * 64) +
                     (kh * 4 + ch));
        }
        // B: 768 tasks: ch(4) x o(64) x dj(3)
        #pragma unroll
        for (int it = 0; it < 3; it++) {
            const int task = tid + it * 256;
            const int ch = task & 3, o = (task >> 2) & 63, dj = task >> 8;
            cp16(bufbase + BOFF + (uint32_t)dj * BTL + (uint32_t)o * ASTR + ch * 16,
                 (const uint4*)(g_w + ((size_t)((di * 3 + dj) * 64 + o)) * 64) +
                     (kh * 4 + ch));
        }
        cp_commit();
    };

    issue_unit(ulist[0], sb);
    if (nunits > 1) issue_unit(ulist[1], sb + UNIT);

    #pragma unroll 1
    for (int u = 0; u < nunits; u++) {
        if (u + 1 < nunits) cp_wait1(); else cp_wait0();
        __syncthreads();

        const uint32_t bufbase = sb + (uint32_t)(u & 1) * UNIT;
        #pragma unroll 1
        for (int dj = 0; dj < 3; dj++) {
            const uint32_t bb = bufbase + BOFF + (uint32_t)dj * BTL;
            #pragma unroll
            for (int k0 = 0; k0 < 32; k0 += 16) {
                uint32_t ahi[2][4], alo[2][4], bf[2][4];
                #pragma unroll
                for (int mi = 0; mi < 2; mi++) {
                    const uint32_t arow =
                        (uint32_t)(m0 + mi * 16 + a_row + dj) * ASTR +
                        (uint32_t)(k0 + a_koff) * 2;
                    ldsm_x4(ahi[mi], bufbase + arow);
                    ldsm_x4(alo[mi], bufbase + APL + arow);
                }
                #pragma unroll
                for (int ni = 0; ni < 2; ni++) {
                    const uint32_t brow =
                        (uint32_t)(n0 + ni * 16 + b_orow) * ASTR +
                        (uint32_t)(k0 + b_koff) * 2;
                    ldsm_x4(bf[ni], bb + brow);
                }
                #pragma unroll
                for (int mi = 0; mi < 2; mi++)
                    #pragma unroll
                    for (int nj = 0; nj < 4; nj++) {
                        mma16816(acc[mi][nj], ahi[mi], &bf[nj >> 1][(nj & 1) * 2]);
                        mma16816(acc[mi][nj], alo[mi], &bf[nj >> 1][(nj & 1) * 2]);
                    }
            }
        }
        __syncthreads();
        if (u + 2 < nunits) issue_unit(ulist[u + 2], bufbase);
    }

    // ---- epilogue ----
    const int orow = lane >> 2, opair = (lane & 3) * 2;
    #pragma unroll
    for (int nj = 0; nj < 4; nj++) {
        const int o = n0 + nj * 8 + opair;
        const float bv0 = bias[o], bv1 = bias[o + 1];
        float* p0 = out + (((size_t)(b * 64 + o)) * 128 + h) * 128;
        float* p1 = p0 + 128 * 128;
        #pragma unroll
        for (int mi = 0; mi < 2; mi++) {
            const int w = m0 + mi * 16 + orow;
            p0[w]     = acc[mi][nj][0] + bv0;
            p1[w]     = acc[mi][nj][1] + bv1;
            p0[w + 8] = acc[mi][nj][2] + bv0;
            p1[w + 8] = acc[mi][nj][3] + bv1;
        }
    }
}

extern "C" void kernel_launch(void* const* d_in, const int* in_sizes, int n_in,
                              void* d_out, int out_size)
{
    const float* x     = (const float*)d_in[0];  // [4,64,128,128]
    const float* alpha = (const float*)d_in[1];  // [4,1,128,128]
    const float* wgt   = (const float*)d_in[2];  // [64,64,3,3]
    const float* bias  = (const float*)d_in[3];  // [64]
    const float* pa    = (const float*)d_in[4];
    const float* pb    = (const float*)d_in[5];
    const float* pc    = (const float*)d_in[6];
    float* out = (float*)d_out;                  // [4,64,128,128]

    cudaFuncSetAttribute(conv_kernel,
                         cudaFuncAttributeMaxDynamicSharedMemorySize, SMEM_TOTAL);

    prep_kernel<<<BATCH * H_DIM, 256>>>(x, alpha, wgt, pa, pb, pc);
    conv_kernel<<<BATCH * H_DIM, 256, SMEM_TOTAL>>>(bias, out);
}